// round 1
// baseline (speedup 1.0000x reference)
#include <cuda_runtime.h>

// ---------------- problem constants ----------------
#define B_    4
#define TEXT_ 64
#define L0_   32
#define L1_   64
#define S0_   1088          // TEXT + 32*32
#define S1_   4096          // 64*64
#define S_    5184          // S0 + S1
#define H_    1024
#define TH_   3072          // 3*H
#define NH_   16
#define HD_   64
#define BH_   64            // B*NH

// ---------------- scratch (static device globals; no allocation) ----------------
__device__ float g_qkv[(size_t)B_ * S_ * TH_];        // [b*S + s][3H]  (q|k|v per head-col blocks)
__device__ float g_scores[(size_t)BH_ * S0_ * S0_];   // branch0 scores/probs
__device__ float g_ctx[(size_t)B_ * S_ * H_];         // concatenated context

// =====================================================================
// Generic tiled SGEMM (NN): C = A @ W (+bias), 128x128 tile, 16-K chunks
// Per-z base offsets: ptr += (z%zmod)*Lo + (z/zmod)*Hi
// causal!=0 caps K at (mTileStart+128)  (A rows are zero beyond diagonal pad)
// =====================================================================
__global__ __launch_bounds__(256) void sgemm_nn(
    const float* __restrict__ A, int lda,
    const float* __restrict__ W, int ldw,
    const float* __restrict__ bias,
    float* __restrict__ C, int ldc,
    int M, int N, int K,
    long aLo, long aHi, long wLo, long wHi, long cLo, long cHi,
    int zmod, int causal)
{
    const int z  = blockIdx.z;
    const int zl = z % zmod, zh = z / zmod;
    A += zl * aLo + zh * aHi;
    W += zl * wLo + zh * wHi;
    C += zl * cLo + zh * cHi;

    __shared__ float As[16][128];
    __shared__ float Ws[16][128];

    const int tid = threadIdx.x;
    const int m0  = blockIdx.y * 128;
    const int n0  = blockIdx.x * 128;
    const int tr  = tid >> 4;      // 0..15
    const int tc  = tid & 15;      // 0..15

    float acc[8][8];
#pragma unroll
    for (int i = 0; i < 8; i++)
#pragma unroll
        for (int j = 0; j < 8; j++) acc[i][j] = 0.f;

    const int kEnd = causal ? min(K, m0 + 128) : K;

    for (int k0 = 0; k0 < kEnd; k0 += 16) {
        // A tile: 128 rows x 16 k, stored transposed As[k][m]
#pragma unroll
        for (int l = 0; l < 2; l++) {
            int idx = tid + l * 256;
            int row = idx >> 2;
            int kq  = (idx & 3) << 2;
            float4 v = make_float4(0.f, 0.f, 0.f, 0.f);
            if (m0 + row < M)
                v = *(const float4*)(A + (long)(m0 + row) * lda + k0 + kq);
            As[kq + 0][row] = v.x; As[kq + 1][row] = v.y;
            As[kq + 2][row] = v.z; As[kq + 3][row] = v.w;
        }
        // W tile: 16 k-rows x 128 n
#pragma unroll
        for (int l = 0; l < 2; l++) {
            int idx = tid + l * 256;
            int kr  = idx >> 5;
            int nq  = (idx & 31) << 2;
            float4 v = make_float4(0.f, 0.f, 0.f, 0.f);
            if (n0 + nq < N)
                v = *(const float4*)(W + (long)(k0 + kr) * ldw + n0 + nq);
            *(float4*)&Ws[kr][nq] = v;
        }
        __syncthreads();
#pragma unroll
        for (int kk = 0; kk < 16; kk++) {
            float ra[8], rw[8];
#pragma unroll
            for (int i = 0; i < 8; i++) ra[i] = As[kk][tr * 8 + i];
#pragma unroll
            for (int j = 0; j < 8; j++) rw[j] = Ws[kk][tc * 8 + j];
#pragma unroll
            for (int i = 0; i < 8; i++)
#pragma unroll
                for (int j = 0; j < 8; j++)
                    acc[i][j] += ra[i] * rw[j];
        }
        __syncthreads();
    }

#pragma unroll
    for (int i = 0; i < 8; i++) {
        int r = m0 + tr * 8 + i;
        if (r >= M) continue;
#pragma unroll
        for (int j = 0; j < 8; j += 4) {
            int c = n0 + tc * 8 + j;
            if (c >= N) continue;
            float4 v;
            v.x = acc[i][j]; v.y = acc[i][j + 1]; v.z = acc[i][j + 2]; v.w = acc[i][j + 3];
            if (bias) { v.x += bias[c]; v.y += bias[c + 1]; v.z += bias[c + 2]; v.w += bias[c + 3]; }
            *(float4*)(C + (long)r * ldc + c) = v;
        }
    }
}

// =====================================================================
// Branch-0 scores: SC[bh][i][j] = (1/8) * q_i . k_j   (NT, K=64)
// Skips tiles entirely above the causal diagonal.
// =====================================================================
__global__ __launch_bounds__(256) void scores_nt()
{
    const int z = blockIdx.z;
    const int b = z >> 4, h = z & 15;
    const float* Qb = g_qkv + (long)b * S_ * TH_ + h * HD_;
    const float* Kb = Qb + H_;   // k block at column offset H
    float* C = g_scores + (long)z * S0_ * S0_;

    const int m0 = blockIdx.y * 128;
    const int n0 = blockIdx.x * 128;
    if (n0 > m0 + 127) return;   // fully masked tile

    __shared__ float As[16][128];
    __shared__ float Bs[16][128];

    const int tid = threadIdx.x;
    const int tr = tid >> 4, tc = tid & 15;

    float acc[8][8];
#pragma unroll
    for (int i = 0; i < 8; i++)
#pragma unroll
        for (int j = 0; j < 8; j++) acc[i][j] = 0.f;

    for (int k0 = 0; k0 < 64; k0 += 16) {
#pragma unroll
        for (int l = 0; l < 2; l++) {
            int idx = tid + l * 256;
            int row = idx >> 2;
            int kq  = (idx & 3) << 2;
            float4 va = make_float4(0.f, 0.f, 0.f, 0.f);
            float4 vb = make_float4(0.f, 0.f, 0.f, 0.f);
            if (m0 + row < S0_)
                va = *(const float4*)(Qb + (long)(m0 + row) * TH_ + k0 + kq);
            if (n0 + row < S0_)
                vb = *(const float4*)(Kb + (long)(n0 + row) * TH_ + k0 + kq);
            As[kq + 0][row] = va.x; As[kq + 1][row] = va.y;
            As[kq + 2][row] = va.z; As[kq + 3][row] = va.w;
            Bs[kq + 0][row] = vb.x; Bs[kq + 1][row] = vb.y;
            Bs[kq + 2][row] = vb.z; Bs[kq + 3][row] = vb.w;
        }
        __syncthreads();
#pragma unroll
        for (int kk = 0; kk < 16; kk++) {
            float ra[8], rb[8];
#pragma unroll
            for (int i = 0; i < 8; i++) ra[i] = As[kk][tr * 8 + i];
#pragma unroll
            for (int j = 0; j < 8; j++) rb[j] = Bs[kk][tc * 8 + j];
#pragma unroll
            for (int i = 0; i < 8; i++)
#pragma unroll
                for (int j = 0; j < 8; j++)
                    acc[i][j] += ra[i] * rb[j];
        }
        __syncthreads();
    }

#pragma unroll
    for (int i = 0; i < 8; i++) {
        int r = m0 + tr * 8 + i;
        if (r >= S0_) continue;
#pragma unroll
        for (int j = 0; j < 8; j += 4) {
            int c = n0 + tc * 8 + j;
            if (c >= S0_) continue;
            float4 v;
            v.x = acc[i][j] * 0.125f;     v.y = acc[i][j + 1] * 0.125f;
            v.z = acc[i][j + 2] * 0.125f; v.w = acc[i][j + 3] * 0.125f;
            *(float4*)(C + (long)r * S0_ + c) = v;
        }
    }
}

// =====================================================================
// Branch-0 causal row softmax, in place. Also zeroes probs for
// j in (i, tileEnd) so the PV GEMM can read full K-tiles.
// =====================================================================
__global__ __launch_bounds__(128) void softmax_causal()
{
    const int i  = blockIdx.x;
    const int bh = blockIdx.y;
    float* row = g_scores + ((long)bh * S0_ + i) * S0_;
    const int n = i + 1;
    const int t = threadIdx.x;
    __shared__ float red[128];

    float m = -1e30f;
    for (int j = t; j < n; j += 128) m = fmaxf(m, row[j]);
    red[t] = m; __syncthreads();
    for (int s = 64; s > 0; s >>= 1) { if (t < s) red[t] = fmaxf(red[t], red[t + s]); __syncthreads(); }
    m = red[0]; __syncthreads();

    float sum = 0.f;
    for (int j = t; j < n; j += 128) { float e = __expf(row[j] - m); row[j] = e; sum += e; }
    red[t] = sum; __syncthreads();
    for (int s = 64; s > 0; s >>= 1) { if (t < s) red[t] += red[t + s]; __syncthreads(); }
    const float inv = 1.0f / red[0];
    __syncthreads();

    for (int j = t; j < n; j += 128) row[j] *= inv;

    // zero the causal pad up to the PV K-cap for this row's M-tile
    const int padEnd = min(S0_, (i / 128) * 128 + 128);
    for (int j = n + t; j < padEnd; j += 128) row[j] = 0.f;
}

// =====================================================================
// Branch-1 fused local attention: one warp per query position.
// 49 cross offsets into the 32x32 grid (last 1024 tokens of branch0 k/v)
// + 77 causal offsets into the 64x64 grid; softmax over all 126
// (out-of-bounds => score 0, v contribution 0, matching zero-padding).
// =====================================================================
__global__ __launch_bounds__(128) void local_attn()
{
    const int bh = blockIdx.y;
    const int b = bh >> 4, h = bh & 15;
    const int p = (blockIdx.x << 2) + (threadIdx.x >> 5);
    const int lane = threadIdx.x & 31;
    const int y = p >> 6, x = p & 63;

    const float* qb = g_qkv + ((long)(b * S_ + S0_ + p)) * TH_ + h * HD_;
    const float q0 = qb[lane] * 0.125f;
    const float q1 = qb[lane + 32] * 0.125f;

    const long base0 = (long)b * S_ * TH_ + h * HD_;   // + row*TH_ (+H for k, +2H for v)

    float sc[4];
    sc[0] = sc[1] = sc[2] = sc[3] = 0.f;

#pragma unroll
    for (int o = 0; o < 126; o++) {
        int row = -1;
        if (o < 49) {
            const int dy = o / 7 - 3, dx = o % 7 - 3;
            const int yi = (y >> 1) + dy, xi = (x >> 1) + dx;
            if ((unsigned)yi < 32u && (unsigned)xi < 32u) row = TEXT_ + yi * L0_ + xi;
        } else {
            const int oc = o - 49;
            const int dy = oc / 9 - 8, dx = oc % 9 - 4;
            const int yy = y + dy, xx = x + dx;
            if ((unsigned)yy < 64u && (unsigned)xx < 64u) row = S0_ + yy * L1_ + xx;
        }
        float s = 0.f;
        if (row >= 0) {
            const float* kk = g_qkv + base0 + (long)row * TH_ + H_;
            s = q0 * kk[lane] + q1 * kk[lane + 32];
        }
#pragma unroll
        for (int d = 16; d > 0; d >>= 1) s += __shfl_xor_sync(0xffffffffu, s, d);
        if (lane == (o & 31)) sc[o >> 5] = s;
    }

    // softmax over the 126 scores (distributed: slot t holds index t*32+lane)
    float m = -1e30f;
#pragma unroll
    for (int t = 0; t < 4; t++) if (t * 32 + lane < 126) m = fmaxf(m, sc[t]);
#pragma unroll
    for (int d = 16; d > 0; d >>= 1) m = fmaxf(m, __shfl_xor_sync(0xffffffffu, m, d));
    float sum = 0.f;
#pragma unroll
    for (int t = 0; t < 4; t++) {
        float e = (t * 32 + lane < 126) ? __expf(sc[t] - m) : 0.f;
        sc[t] = e; sum += e;
    }
#pragma unroll
    for (int d = 16; d > 0; d >>= 1) sum += __shfl_xor_sync(0xffffffffu, sum, d);
    const float inv = 1.0f / sum;

    float a0 = 0.f, a1 = 0.f;
#pragma unroll
    for (int o = 0; o < 126; o++) {
        const float pv = __shfl_sync(0xffffffffu, sc[o >> 5], o & 31) * inv;
        int row = -1;
        if (o < 49) {
            const int dy = o / 7 - 3, dx = o % 7 - 3;
            const int yi = (y >> 1) + dy, xi = (x >> 1) + dx;
            if ((unsigned)yi < 32u && (unsigned)xi < 32u) row = TEXT_ + yi * L0_ + xi;
        } else {
            const int oc = o - 49;
            const int dy = oc / 9 - 8, dx = oc % 9 - 4;
            const int yy = y + dy, xx = x + dx;
            if ((unsigned)yy < 64u && (unsigned)xx < 64u) row = S0_ + yy * L1_ + xx;
        }
        if (row >= 0) {
            const float* vv = g_qkv + base0 + (long)row * TH_ + 2 * H_;
            a0 += pv * vv[lane];
            a1 += pv * vv[lane + 32];
        }
    }

    float* cb = g_ctx + ((long)(b * S_ + S0_ + p)) * H_ + h * HD_;
    cb[lane] = a0;
    cb[lane + 32] = a1;
}

// =====================================================================
// host launcher
// =====================================================================
extern "C" void kernel_launch(void* const* d_in, const int* in_sizes, int n_in,
                              void* d_out, int out_size)
{
    const float* hs      = (const float*)d_in[0];
    // d_in[1] = mask (unused; causal handled analytically)
    const float* W_qkv   = (const float*)d_in[2];
    const float* b_qkv   = (const float*)d_in[3];
    const float* W_qkvp  = (const float*)d_in[4];
    const float* b_qkvp  = (const float*)d_in[5];
    const float* W_dense = (const float*)d_in[6];
    const float* b_dense = (const float*)d_in[7];
    float* out = (float*)d_out;

    float *qkvp, *scp, *ctxp;
    cudaGetSymbolAddress((void**)&qkvp, g_qkv);
    cudaGetSymbolAddress((void**)&scp,  g_scores);
    cudaGetSymbolAddress((void**)&ctxp, g_ctx);
    (void)scp; (void)in_sizes; (void)n_in; (void)out_size;

    // 1) QKV branch0: per batch, rows 0..S0-1
    sgemm_nn<<<dim3(TH_ / 128, (S0_ + 127) / 128, B_), 256>>>(
        hs, H_, W_qkv, TH_, b_qkv, qkvp, TH_,
        S0_, TH_, H_,
        0, (long)S_ * H_, 0, 0, 0, (long)S_ * TH_, 1, 0);

    // 2) QKV branch1: per batch, rows S0..S-1
    sgemm_nn<<<dim3(TH_ / 128, S1_ / 128, B_), 256>>>(
        hs + (long)S0_ * H_, H_, W_qkvp, TH_, b_qkvp, qkvp + (long)S0_ * TH_, TH_,
        S1_, TH_, H_,
        0, (long)S_ * H_, 0, 0, 0, (long)S_ * TH_, 1, 0);

    // 3) branch0 scores (NT, causal tile skip)
    scores_nt<<<dim3((S0_ + 127) / 128, (S0_ + 127) / 128, BH_), 256>>>();

    // 4) causal softmax
    softmax_causal<<<dim3(S0_, BH_), 128>>>();

    // 5) PV: ctx0 = probs @ V   (causal K-cap; per-bh strided V/C bases)
    sgemm_nn<<<dim3(1, (S0_ + 127) / 128, BH_), 256>>>(
        scp, S0_, qkvp + 2 * H_, TH_, nullptr, ctxp, H_,
        S0_, HD_, S0_,
        (long)S0_ * S0_, (long)NH_ * S0_ * S0_,     // A: +h*S0^2, +b*16*S0^2
        HD_, (long)S_ * TH_,                         // W(V): +h*64, +b*S*3H
        HD_, (long)S_ * H_,                          // C:    +h*64, +b*S*H
        NH_, 1);

    // 6) branch1 fused local attention
    local_attn<<<dim3(S1_ / 4, BH_), 128>>>();

    // 7) dense output projection over all rows
    sgemm_nn<<<dim3(H_ / 128, (B_ * S_) / 128, 1), 256>>>(
        ctxp, H_, W_dense, H_, b_dense, out, H_,
        B_ * S_, H_, H_,
        0, 0, 0, 0, 0, 0, 1, 0);
}

// round 2
// speedup vs baseline: 1.3652x; 1.3652x over previous
#include <cuda_runtime.h>
#include <cstdint>

// ---------------- problem constants ----------------
#define B_    4
#define TEXT_ 64
#define L0_   32
#define L1_   64
#define S0_   1088          // TEXT + 32*32
#define S1_   4096          // 64*64
#define S_    5184          // S0 + S1
#define H_    1024
#define TH_   3072          // 3*H
#define NH_   16
#define HD_   64
#define BH_   64            // B*NH

// ---------------- scratch (static device globals; no allocation) ----------------
__device__ float g_qkv[(size_t)B_ * S_ * TH_];        // [b*S + s][3H]  (q|k|v per head-col blocks)
__device__ float g_scores[(size_t)BH_ * S0_ * S0_];   // branch0 scores/probs
__device__ float g_ctx[(size_t)B_ * S_ * H_];         // concatenated context

__device__ __forceinline__ uint32_t f2tf32(float f) {
    uint32_t r;
    asm("cvt.rna.tf32.f32 %0, %1;" : "=r"(r) : "f"(f));
    return r;
}

// =====================================================================
// TF32 tensor-core SGEMM (NN): C = A @ W (+bias)
// 128x128 tile, K-chunk 32, 256 threads = 8 warps (4x2), warp tile 32x64.
// mma.sync.aligned.m16n8k8.row.col.f32.tf32.tf32.f32
// Smem pads chosen for conflict-free fragment LDS.
// =====================================================================
__global__ __launch_bounds__(256, 1) void tgemm_nn(
    const float* __restrict__ A, int lda,
    const float* __restrict__ W, int ldw,
    const float* __restrict__ bias,
    float* __restrict__ C, int ldc,
    int M, int N, int K,
    long aHi, long cHi)
{
    const int z = blockIdx.z;
    A += (long)z * aHi;
    C += (long)z * cHi;

    __shared__ uint32_t As[128][36];   // [m][k] pad 4: banks = 4*row + k
    __shared__ uint32_t Bs[32][136];   // [k][n] pad 8: banks = 8*k + n

    const int tid   = threadIdx.x;
    const int warp  = tid >> 5;
    const int lane  = tid & 31;
    const int wm    = warp >> 1;       // 0..3  -> 32 rows each
    const int wn    = warp & 1;        // 0..1  -> 64 cols each
    const int m0    = blockIdx.y * 128;
    const int n0    = blockIdx.x * 128;

    const int grp = lane >> 2;         // 0..7
    const int tg  = lane & 3;          // 0..3

    float acc[2][8][4];
#pragma unroll
    for (int i = 0; i < 2; i++)
#pragma unroll
        for (int j = 0; j < 8; j++)
#pragma unroll
            for (int c = 0; c < 4; c++) acc[i][j][c] = 0.f;

    for (int k0 = 0; k0 < K; k0 += 32) {
        // A tile: 128 x 32 -> As[m][k]
#pragma unroll
        for (int l = 0; l < 4; l++) {
            int q   = tid + l * 256;           // quad index over 1024
            int row = q >> 3;
            int kq  = (q & 7) << 2;
            float4 v = make_float4(0.f, 0.f, 0.f, 0.f);
            if (m0 + row < M)
                v = *(const float4*)(A + (long)(m0 + row) * lda + k0 + kq);
            As[row][kq + 0] = f2tf32(v.x);
            As[row][kq + 1] = f2tf32(v.y);
            As[row][kq + 2] = f2tf32(v.z);
            As[row][kq + 3] = f2tf32(v.w);
        }
        // W tile: 32 x 128 -> Bs[k][n]
#pragma unroll
        for (int l = 0; l < 4; l++) {
            int q  = tid + l * 256;
            int kr = q >> 5;
            int nq = (q & 31) << 2;
            float4 v = *(const float4*)(W + (long)(k0 + kr) * ldw + n0 + nq);
            Bs[kr][nq + 0] = f2tf32(v.x);
            Bs[kr][nq + 1] = f2tf32(v.y);
            Bs[kr][nq + 2] = f2tf32(v.z);
            Bs[kr][nq + 3] = f2tf32(v.w);
        }
        __syncthreads();

#pragma unroll
        for (int ks = 0; ks < 4; ks++) {
            const int kb = ks * 8;
            uint32_t af[2][4];
#pragma unroll
            for (int mi = 0; mi < 2; mi++) {
                const int r = wm * 32 + mi * 16 + grp;
                af[mi][0] = As[r    ][kb + tg];
                af[mi][1] = As[r + 8][kb + tg];
                af[mi][2] = As[r    ][kb + tg + 4];
                af[mi][3] = As[r + 8][kb + tg + 4];
            }
            uint32_t bf[8][2];
#pragma unroll
            for (int ni = 0; ni < 8; ni++) {
                const int c = wn * 64 + ni * 8 + grp;
                bf[ni][0] = Bs[kb + tg    ][c];
                bf[ni][1] = Bs[kb + tg + 4][c];
            }
#pragma unroll
            for (int mi = 0; mi < 2; mi++)
#pragma unroll
                for (int ni = 0; ni < 8; ni++) {
                    asm volatile(
                        "mma.sync.aligned.m16n8k8.row.col.f32.tf32.tf32.f32 "
                        "{%0,%1,%2,%3}, {%4,%5,%6,%7}, {%8,%9}, {%0,%1,%2,%3};"
                        : "+f"(acc[mi][ni][0]), "+f"(acc[mi][ni][1]),
                          "+f"(acc[mi][ni][2]), "+f"(acc[mi][ni][3])
                        : "r"(af[mi][0]), "r"(af[mi][1]), "r"(af[mi][2]), "r"(af[mi][3]),
                          "r"(bf[ni][0]), "r"(bf[ni][1]));
                }
        }
        __syncthreads();
    }

    // epilogue
#pragma unroll
    for (int mi = 0; mi < 2; mi++) {
#pragma unroll
        for (int ni = 0; ni < 8; ni++) {
            const int col = n0 + wn * 64 + ni * 8 + tg * 2;
            float bx = 0.f, by = 0.f;
            if (bias) { bx = bias[col]; by = bias[col + 1]; }
            const int r0 = m0 + wm * 32 + mi * 16 + grp;
            if (r0 < M) {
                float2 v; v.x = acc[mi][ni][0] + bx; v.y = acc[mi][ni][1] + by;
                *(float2*)(C + (long)r0 * ldc + col) = v;
            }
            const int r1 = r0 + 8;
            if (r1 < M) {
                float2 v; v.x = acc[mi][ni][2] + bx; v.y = acc[mi][ni][3] + by;
                *(float2*)(C + (long)r1 * ldc + col) = v;
            }
        }
    }
}

// =====================================================================
// Generic tiled FP32 SGEMM (NN) — kept for the PV GEMM (small FLOPs,
// fp32 accuracy). 128x128 tile, 16-K chunks.
// =====================================================================
__global__ __launch_bounds__(256) void sgemm_nn(
    const float* __restrict__ A, int lda,
    const float* __restrict__ W, int ldw,
    const float* __restrict__ bias,
    float* __restrict__ C, int ldc,
    int M, int N, int K,
    long aLo, long aHi, long wLo, long wHi, long cLo, long cHi,
    int zmod, int causal)
{
    const int z  = blockIdx.z;
    const int zl = z % zmod, zh = z / zmod;
    A += zl * aLo + zh * aHi;
    W += zl * wLo + zh * wHi;
    C += zl * cLo + zh * cHi;

    __shared__ float As[16][128];
    __shared__ float Ws[16][128];

    const int tid = threadIdx.x;
    const int m0  = blockIdx.y * 128;
    const int n0  = blockIdx.x * 128;
    const int tr  = tid >> 4;
    const int tc  = tid & 15;

    float acc[8][8];
#pragma unroll
    for (int i = 0; i < 8; i++)
#pragma unroll
        for (int j = 0; j < 8; j++) acc[i][j] = 0.f;

    const int kEnd = causal ? min(K, m0 + 128) : K;

    for (int k0 = 0; k0 < kEnd; k0 += 16) {
#pragma unroll
        for (int l = 0; l < 2; l++) {
            int idx = tid + l * 256;
            int row = idx >> 2;
            int kq  = (idx & 3) << 2;
            float4 v = make_float4(0.f, 0.f, 0.f, 0.f);
            if (m0 + row < M)
                v = *(const float4*)(A + (long)(m0 + row) * lda + k0 + kq);
            As[kq + 0][row] = v.x; As[kq + 1][row] = v.y;
            As[kq + 2][row] = v.z; As[kq + 3][row] = v.w;
        }
#pragma unroll
        for (int l = 0; l < 2; l++) {
            int idx = tid + l * 256;
            int kr  = idx >> 5;
            int nq  = (idx & 31) << 2;
            float4 v = make_float4(0.f, 0.f, 0.f, 0.f);
            if (n0 + nq < N)
                v = *(const float4*)(W + (long)(k0 + kr) * ldw + n0 + nq);
            *(float4*)&Ws[kr][nq] = v;
        }
        __syncthreads();
#pragma unroll
        for (int kk = 0; kk < 16; kk++) {
            float ra[8], rw[8];
#pragma unroll
            for (int i = 0; i < 8; i++) ra[i] = As[kk][tr * 8 + i];
#pragma unroll
            for (int j = 0; j < 8; j++) rw[j] = Ws[kk][tc * 8 + j];
#pragma unroll
            for (int i = 0; i < 8; i++)
#pragma unroll
                for (int j = 0; j < 8; j++)
                    acc[i][j] += ra[i] * rw[j];
        }
        __syncthreads();
    }

#pragma unroll
    for (int i = 0; i < 8; i++) {
        int r = m0 + tr * 8 + i;
        if (r >= M) continue;
#pragma unroll
        for (int j = 0; j < 8; j += 4) {
            int c = n0 + tc * 8 + j;
            if (c >= N) continue;
            float4 v;
            v.x = acc[i][j]; v.y = acc[i][j + 1]; v.z = acc[i][j + 2]; v.w = acc[i][j + 3];
            if (bias) { v.x += bias[c]; v.y += bias[c + 1]; v.z += bias[c + 2]; v.w += bias[c + 3]; }
            *(float4*)(C + (long)r * ldc + c) = v;
        }
    }
}

// =====================================================================
// Branch-0 scores: SC[bh][i][j] = (1/8) * q_i . k_j   (NT, K=64)
// Skips tiles entirely above the causal diagonal.
// =====================================================================
__global__ __launch_bounds__(256) void scores_nt()
{
    const int z = blockIdx.z;
    const int b = z >> 4, h = z & 15;
    const float* Qb = g_qkv + (long)b * S_ * TH_ + h * HD_;
    const float* Kb = Qb + H_;
    float* C = g_scores + (long)z * S0_ * S0_;

    const int m0 = blockIdx.y * 128;
    const int n0 = blockIdx.x * 128;
    if (n0 > m0 + 127) return;

    __shared__ float As[16][128];
    __shared__ float Bs[16][128];

    const int tid = threadIdx.x;
    const int tr = tid >> 4, tc = tid & 15;

    float acc[8][8];
#pragma unroll
    for (int i = 0; i < 8; i++)
#pragma unroll
        for (int j = 0; j < 8; j++) acc[i][j] = 0.f;

    for (int k0 = 0; k0 < 64; k0 += 16) {
#pragma unroll
        for (int l = 0; l < 2; l++) {
            int idx = tid + l * 256;
            int row = idx >> 2;
            int kq  = (idx & 3) << 2;
            float4 va = make_float4(0.f, 0.f, 0.f, 0.f);
            float4 vb = make_float4(0.f, 0.f, 0.f, 0.f);
            if (m0 + row < S0_)
                va = *(const float4*)(Qb + (long)(m0 + row) * TH_ + k0 + kq);
            if (n0 + row < S0_)
                vb = *(const float4*)(Kb + (long)(n0 + row) * TH_ + k0 + kq);
            As[kq + 0][row] = va.x; As[kq + 1][row] = va.y;
            As[kq + 2][row] = va.z; As[kq + 3][row] = va.w;
            Bs[kq + 0][row] = vb.x; Bs[kq + 1][row] = vb.y;
            Bs[kq + 2][row] = vb.z; Bs[kq + 3][row] = vb.w;
        }
        __syncthreads();
#pragma unroll
        for (int kk = 0; kk < 16; kk++) {
            float ra[8], rb[8];
#pragma unroll
            for (int i = 0; i < 8; i++) ra[i] = As[kk][tr * 8 + i];
#pragma unroll
            for (int j = 0; j < 8; j++) rb[j] = Bs[kk][tc * 8 + j];
#pragma unroll
            for (int i = 0; i < 8; i++)
#pragma unroll
                for (int j = 0; j < 8; j++)
                    acc[i][j] += ra[i] * rb[j];
        }
        __syncthreads();
    }

#pragma unroll
    for (int i = 0; i < 8; i++) {
        int r = m0 + tr * 8 + i;
        if (r >= S0_) continue;
#pragma unroll
        for (int j = 0; j < 8; j += 4) {
            int c = n0 + tc * 8 + j;
            if (c >= S0_) continue;
            float4 v;
            v.x = acc[i][j] * 0.125f;     v.y = acc[i][j + 1] * 0.125f;
            v.z = acc[i][j + 2] * 0.125f; v.w = acc[i][j + 3] * 0.125f;
            *(float4*)(C + (long)r * S0_ + c) = v;
        }
    }
}

// =====================================================================
// Branch-0 causal row softmax, in place + zero pad to PV K-cap.
// =====================================================================
__global__ __launch_bounds__(128) void softmax_causal()
{
    const int i  = blockIdx.x;
    const int bh = blockIdx.y;
    float* row = g_scores + ((long)bh * S0_ + i) * S0_;
    const int n = i + 1;
    const int t = threadIdx.x;
    __shared__ float red[128];

    float m = -1e30f;
    for (int j = t; j < n; j += 128) m = fmaxf(m, row[j]);
    red[t] = m; __syncthreads();
    for (int s = 64; s > 0; s >>= 1) { if (t < s) red[t] = fmaxf(red[t], red[t + s]); __syncthreads(); }
    m = red[0]; __syncthreads();

    float sum = 0.f;
    for (int j = t; j < n; j += 128) { float e = __expf(row[j] - m); row[j] = e; sum += e; }
    red[t] = sum; __syncthreads();
    for (int s = 64; s > 0; s >>= 1) { if (t < s) red[t] += red[t + s]; __syncthreads(); }
    const float inv = 1.0f / red[0];
    __syncthreads();

    for (int j = t; j < n; j += 128) row[j] *= inv;

    const int padEnd = min(S0_, (i / 128) * 128 + 128);
    for (int j = n + t; j < padEnd; j += 128) row[j] = 0.f;
}

// =====================================================================
// Branch-1 fused local attention: one warp per query position.
// =====================================================================
__global__ __launch_bounds__(128) void local_attn()
{
    const int bh = blockIdx.y;
    const int b = bh >> 4, h = bh & 15;
    const int p = (blockIdx.x << 2) + (threadIdx.x >> 5);
    const int lane = threadIdx.x & 31;
    const int y = p >> 6, x = p & 63;

    const float* qb = g_qkv + ((long)(b * S_ + S0_ + p)) * TH_ + h * HD_;
    const float q0 = qb[lane] * 0.125f;
    const float q1 = qb[lane + 32] * 0.125f;

    const long base0 = (long)b * S_ * TH_ + h * HD_;

    float sc[4];
    sc[0] = sc[1] = sc[2] = sc[3] = 0.f;

#pragma unroll
    for (int o = 0; o < 126; o++) {
        int row = -1;
        if (o < 49) {
            const int dy = o / 7 - 3, dx = o % 7 - 3;
            const int yi = (y >> 1) + dy, xi = (x >> 1) + dx;
            if ((unsigned)yi < 32u && (unsigned)xi < 32u) row = TEXT_ + yi * L0_ + xi;
        } else {
            const int oc = o - 49;
            const int dy = oc / 9 - 8, dx = oc % 9 - 4;
            const int yy = y + dy, xx = x + dx;
            if ((unsigned)yy < 64u && (unsigned)xx < 64u) row = S0_ + yy * L1_ + xx;
        }
        float s = 0.f;
        if (row >= 0) {
            const float* kk = g_qkv + base0 + (long)row * TH_ + H_;
            s = q0 * kk[lane] + q1 * kk[lane + 32];
        }
#pragma unroll
        for (int d = 16; d > 0; d >>= 1) s += __shfl_xor_sync(0xffffffffu, s, d);
        if (lane == (o & 31)) sc[o >> 5] = s;
    }

    float m = -1e30f;
#pragma unroll
    for (int t = 0; t < 4; t++) if (t * 32 + lane < 126) m = fmaxf(m, sc[t]);
#pragma unroll
    for (int d = 16; d > 0; d >>= 1) m = fmaxf(m, __shfl_xor_sync(0xffffffffu, m, d));
    float sum = 0.f;
#pragma unroll
    for (int t = 0; t < 4; t++) {
        float e = (t * 32 + lane < 126) ? __expf(sc[t] - m) : 0.f;
        sc[t] = e; sum += e;
    }
#pragma unroll
    for (int d = 16; d > 0; d >>= 1) sum += __shfl_xor_sync(0xffffffffu, sum, d);
    const float inv = 1.0f / sum;

    float a0 = 0.f, a1 = 0.f;
#pragma unroll
    for (int o = 0; o < 126; o++) {
        const float pv = __shfl_sync(0xffffffffu, sc[o >> 5], o & 31) * inv;
        int row = -1;
        if (o < 49) {
            const int dy = o / 7 - 3, dx = o % 7 - 3;
            const int yi = (y >> 1) + dy, xi = (x >> 1) + dx;
            if ((unsigned)yi < 32u && (unsigned)xi < 32u) row = TEXT_ + yi * L0_ + xi;
        } else {
            const int oc = o - 49;
            const int dy = oc / 9 - 8, dx = oc % 9 - 4;
            const int yy = y + dy, xx = x + dx;
            if ((unsigned)yy < 64u && (unsigned)xx < 64u) row = S0_ + yy * L1_ + xx;
        }
        if (row >= 0) {
            const float* vv = g_qkv + base0 + (long)row * TH_ + 2 * H_;
            a0 += pv * vv[lane];
            a1 += pv * vv[lane + 32];
        }
    }

    float* cb = g_ctx + ((long)(b * S_ + S0_ + p)) * H_ + h * HD_;
    cb[lane] = a0;
    cb[lane + 32] = a1;
}

// =====================================================================
// host launcher
// =====================================================================
extern "C" void kernel_launch(void* const* d_in, const int* in_sizes, int n_in,
                              void* d_out, int out_size)
{
    const float* hs      = (const float*)d_in[0];
    const float* W_qkv   = (const float*)d_in[2];
    const float* b_qkv   = (const float*)d_in[3];
    const float* W_qkvp  = (const float*)d_in[4];
    const float* b_qkvp  = (const float*)d_in[5];
    const float* W_dense = (const float*)d_in[6];
    const float* b_dense = (const float*)d_in[7];
    float* out = (float*)d_out;

    float *qkvp, *scp, *ctxp;
    cudaGetSymbolAddress((void**)&qkvp, g_qkv);
    cudaGetSymbolAddress((void**)&scp,  g_scores);
    cudaGetSymbolAddress((void**)&ctxp, g_ctx);
    (void)in_sizes; (void)n_in; (void)out_size;

    // 1) QKV branch0 (tf32 tensor cores): per batch, rows 0..S0-1
    tgemm_nn<<<dim3(TH_ / 128, (S0_ + 127) / 128, B_), 256>>>(
        hs, H_, W_qkv, TH_, b_qkv, qkvp, TH_,
        S0_, TH_, H_,
        (long)S_ * H_, (long)S_ * TH_);

    // 2) QKV branch1 (tf32): per batch, rows S0..S-1
    tgemm_nn<<<dim3(TH_ / 128, S1_ / 128, B_), 256>>>(
        hs + (long)S0_ * H_, H_, W_qkvp, TH_, b_qkvp, qkvp + (long)S0_ * TH_, TH_,
        S1_, TH_, H_,
        (long)S_ * H_, (long)S_ * TH_);

    // 3) branch0 scores (fp32 NT, causal tile skip)
    scores_nt<<<dim3((S0_ + 127) / 128, (S0_ + 127) / 128, BH_), 256>>>();

    // 4) causal softmax
    softmax_causal<<<dim3(S0_, BH_), 128>>>();

    // 5) PV: ctx0 = probs @ V (fp32, causal K-cap)
    sgemm_nn<<<dim3(1, (S0_ + 127) / 128, BH_), 256>>>(
        scp, S0_, qkvp + 2 * H_, TH_, nullptr, ctxp, H_,
        S0_, HD_, S0_,
        (long)S0_ * S0_, (long)NH_ * S0_ * S0_,
        HD_, (long)S_ * TH_,
        HD_, (long)S_ * H_,
        NH_, 1);

    // 6) branch1 fused local attention
    local_attn<<<dim3(S1_ / 4, BH_), 128>>>();

    // 7) dense output projection (tf32) over all rows
    tgemm_nn<<<dim3(H_ / 128, (B_ * S_) / 128, 1), 256>>>(
        ctxp, H_, W_dense, H_, b_dense, out, H_,
        B_ * S_, H_, H_,
        0, 0);
}